// round 1
// baseline (speedup 1.0000x reference)
#include <cuda_runtime.h>

// RoiAlign (TF crop_and_resize, bilinear), fixed problem shape:
//   features: [B=2, H=64, W=64, C=256] fp32
//   rois:     [B=2, N=2000, 4] fp32 normalized (y1,x1,y2,x2)
//   out:      [B, N, 7, 7, C] fp32
constexpr int H = 64;
constexpr int W = 64;
constexpr int C = 256;
constexpr int PH = 7;
constexpr int PW = 7;
constexpr int CV = C / 4;  // float4 groups per pixel = 64

__global__ void __launch_bounds__(256) roialign_kernel(
    const float4* __restrict__ feat,   // [B, H, W, CV] as float4
    const float*  __restrict__ rois,   // [B, N, 4]
    float4*       __restrict__ out,    // [B, N, PH, PW, CV] as float4
    int N, int total)
{
    int tid = blockIdx.x * blockDim.x + threadIdx.x;
    if (tid >= total) return;

    // tid layout == output layout: (((b*N+n)*PH+py)*PW+px)*CV + c4
    int c4   = tid & (CV - 1);
    int rest = tid >> 6;          // CV = 64
    int px   = rest % PW; rest /= PW;
    int py   = rest % PH; rest /= PH;
    int n    = rest % N;
    int b    = rest / N;

    const float* box = rois + ((size_t)b * N + n) * 4;
    float by1 = box[0];
    float bx1 = box[1];
    float by2 = box[2];
    float bx2 = box[3];

    float fy = (float)py / (float)(PH - 1);
    float fx = (float)px / (float)(PW - 1);
    float ys = (by1 + fy * (by2 - by1)) * (float)(H - 1);
    float xs = (bx1 + fx * (bx2 - bx1)) * (float)(W - 1);

    float y0f = fminf(fmaxf(floorf(ys), 0.0f), (float)(H - 1));
    float x0f = fminf(fmaxf(floorf(xs), 0.0f), (float)(W - 1));
    int y0 = (int)y0f;
    int x0 = (int)x0f;
    int y1i = min(y0 + 1, H - 1);
    int x1i = min(x0 + 1, W - 1);
    float wy = ys - y0f;
    float wx = xs - x0f;

    const float4* fb = feat + (size_t)b * H * W * CV;
    float4 f00 = fb[(y0  * W + x0 ) * CV + c4];
    float4 f01 = fb[(y0  * W + x1i) * CV + c4];
    float4 f10 = fb[(y1i * W + x0 ) * CV + c4];
    float4 f11 = fb[(y1i * W + x1i) * CV + c4];

    float4 r;
    {
        float top, bot;
        top = f00.x + (f01.x - f00.x) * wx;
        bot = f10.x + (f11.x - f10.x) * wx;
        r.x = top + (bot - top) * wy;
        top = f00.y + (f01.y - f00.y) * wx;
        bot = f10.y + (f11.y - f10.y) * wx;
        r.y = top + (bot - top) * wy;
        top = f00.z + (f01.z - f00.z) * wx;
        bot = f10.z + (f11.z - f10.z) * wx;
        r.z = top + (bot - top) * wy;
        top = f00.w + (f01.w - f00.w) * wx;
        bot = f10.w + (f11.w - f10.w) * wx;
        r.w = top + (bot - top) * wy;
    }

    out[tid] = r;
}

extern "C" void kernel_launch(void* const* d_in, const int* in_sizes, int n_in,
                              void* d_out, int out_size)
{
    const float* features = (const float*)d_in[0];
    const float* rois     = (const float*)d_in[1];
    float* out            = (float*)d_out;

    const int B = 2;
    int N = in_sizes[1] / (B * 4);               // 2000
    int total = B * N * PH * PW * CV;            // float4 work items

    int block = 256;
    int grid = (total + block - 1) / block;
    roialign_kernel<<<grid, block>>>(
        (const float4*)features, rois, (float4*)out, N, total);
}

// round 2
// speedup vs baseline: 1.0040x; 1.0040x over previous
#include <cuda_runtime.h>

// RoiAlign (TF crop_and_resize, bilinear), fixed problem shape:
//   features: [B=2, H=64, W=64, C=256] fp32
//   rois:     [B=2, N=2000, 4] fp32 normalized (y1,x1,y2,x2)
//   out:      [B, N, 7, 7, C] fp32
constexpr int H = 64;
constexpr int W = 64;
constexpr int C = 256;
constexpr int PH = 7;
constexpr int PW = 7;
constexpr int CV = C / 4;  // float4 groups per pixel = 64

__global__ void __launch_bounds__(256) roialign_kernel(
    const float4* __restrict__ feat,   // [B, H, W, CV] as float4
    const float*  __restrict__ rois,   // [B, N, 4]
    float4*       __restrict__ out,    // [B, N, PH, PW, CV] as float4
    int N, int total)
{
    int tid = blockIdx.x * blockDim.x + threadIdx.x;
    if (tid >= total) return;

    // tid layout == output layout: (((b*N+n)*PH+py)*PW+px)*CV + c4
    int c4   = tid & (CV - 1);
    int rest = tid >> 6;          // CV = 64
    int px   = rest % PW; rest /= PW;
    int py   = rest % PH; rest /= PH;
    int n    = rest % N;
    int b    = rest / N;

    const float* box = rois + ((size_t)b * N + n) * 4;
    float by1 = box[0];
    float bx1 = box[1];
    float by2 = box[2];
    float bx2 = box[3];

    float fy = (float)py / (float)(PH - 1);
    float fx = (float)px / (float)(PW - 1);
    float ys = (by1 + fy * (by2 - by1)) * (float)(H - 1);
    float xs = (bx1 + fx * (bx2 - bx1)) * (float)(W - 1);

    float y0f = fminf(fmaxf(floorf(ys), 0.0f), (float)(H - 1));
    float x0f = fminf(fmaxf(floorf(xs), 0.0f), (float)(W - 1));
    int y0 = (int)y0f;
    int x0 = (int)x0f;
    int y1i = min(y0 + 1, H - 1);
    int x1i = min(x0 + 1, W - 1);
    float wy = ys - y0f;
    float wx = xs - x0f;

    const float4* fb = feat + (size_t)b * H * W * CV;
    float4 f00 = fb[(y0  * W + x0 ) * CV + c4];
    float4 f01 = fb[(y0  * W + x1i) * CV + c4];
    float4 f10 = fb[(y1i * W + x0 ) * CV + c4];
    float4 f11 = fb[(y1i * W + x1i) * CV + c4];

    float4 r;
    {
        float top, bot;
        top = f00.x + (f01.x - f00.x) * wx;
        bot = f10.x + (f11.x - f10.x) * wx;
        r.x = top + (bot - top) * wy;
        top = f00.y + (f01.y - f00.y) * wx;
        bot = f10.y + (f11.y - f10.y) * wx;
        r.y = top + (bot - top) * wy;
        top = f00.z + (f01.z - f00.z) * wx;
        bot = f10.z + (f11.z - f10.z) * wx;
        r.z = top + (bot - top) * wy;
        top = f00.w + (f01.w - f00.w) * wx;
        bot = f10.w + (f11.w - f10.w) * wx;
        r.w = top + (bot - top) * wy;
    }

    out[tid] = r;
}

extern "C" void kernel_launch(void* const* d_in, const int* in_sizes, int n_in,
                              void* d_out, int out_size)
{
    const float* features = (const float*)d_in[0];
    const float* rois     = (const float*)d_in[1];
    float* out            = (float*)d_out;

    const int B = 2;
    int N = in_sizes[1] / (B * 4);               // 2000
    int total = B * N * PH * PW * CV;            // float4 work items

    int block = 256;
    int grid = (total + block - 1) / block;
    roialign_kernel<<<grid, block>>>(
        (const float4*)features, rois, (float4*)out, N, total);
}